// round 11
// baseline (speedup 1.0000x reference)
#include <cuda_runtime.h>
#include <cuda_fp16.h>
#include <math.h>
#include <stdint.h>

// Problem constants
#define Bn    16
#define KDIM  1024
#define PB    ((size_t)1024 * 1024)

// GEMM tiling (R6-proven): CTA tile 128x128, K chunks of 32 halves
#define BK      32
#define NCHUNK  (KDIM / BK)   // 32
#define TILE_B  8192          // bytes per 128x32-half tile (swizzled)
#define OFF_AH  0
#define OFF_AL  (1 * TILE_B)
#define OFF_BH  (2 * TILE_B)
#define OFF_BL  (3 * TILE_B)
#define STG_B   (4 * TILE_B)          // 32 KB / stage
#define NSTG    3
#define SMEM_BYTES (NSTG * STG_B)     // 96 KB

// Task graph
#define NT_G1   1024
#define NT_G2   1024
#define NT_SM   128
#define NT_G3   1024
#define T_G2_0  (NT_G1)
#define T_SM_0  (NT_G1 + NT_G2)
#define T_G3_0  (NT_G1 + NT_G2 + NT_SM)
#define NTASK   (NT_G1 + NT_G2 + NT_SM + NT_G3)   // 3200
#define GRID_P  304

// ---------------------------------------------------------------------------
// Device scratch + task-graph state
// ---------------------------------------------------------------------------
#define ELEMS ((size_t)Bn * 1024 * 1024)
__device__ __half g_Shi[ELEMS], g_Slo[ELEMS];
__device__ __half g_Whi[1024 * 1024], g_Wlo[1024 * 1024];
__device__ __half g_Hhi[ELEMS], g_Hlo[ELEMS];
__device__ __half g_Thi[ELEMS];                   // H transposed (hi only)
__device__ __half g_SPhi[ELEMS], g_SPlo[ELEMS];   // G1 out
__device__ __half g_Phi[ELEMS], g_Plo[ELEMS];     // softmax out
__device__ float  g_score[ELEMS];

__device__ int g_task;
__device__ int g_g1cnt[Bn * 8];
__device__ int g_g2cnt[Bn * 8];
__device__ int g_smflag[Bn * 8];

// ---------------------------------------------------------------------------
// Helpers
// ---------------------------------------------------------------------------
__device__ __forceinline__ uint32_t smem_u32(const void* p) {
    return (uint32_t)__cvta_generic_to_shared(p);
}
__device__ __forceinline__ void cp16(uint32_t dst, const void* src) {
    asm volatile("cp.async.cg.shared.global [%0], [%1], 16;\n"
                 :: "r"(dst), "l"(src) : "memory");
}
#define CP_COMMIT() asm volatile("cp.async.commit_group;\n" ::: "memory")
#define CP_WAIT(n)  asm volatile("cp.async.wait_group %0;\n" :: "n"(n) : "memory")

__device__ __forceinline__ uint32_t swz(uint32_t r, uint32_t c) {
    return (r >> 1) * 128u + (((((r & 1u) << 2) | (c ^ ((r >> 1) & 3u)))) << 4);
}

#define LDSM4(r, a)                                                            \
    asm volatile("ldmatrix.sync.aligned.m8n8.x4.shared.b16 {%0,%1,%2,%3}, [%4];" \
        : "=r"((r)[0]), "=r"((r)[1]), "=r"((r)[2]), "=r"((r)[3]) : "r"(a))

#define MMA16816(c, a, b0v, b1v)                                               \
    asm volatile("mma.sync.aligned.m16n8k16.row.col.f32.f16.f16.f32 "          \
        "{%0,%1,%2,%3}, {%4,%5,%6,%7}, {%8,%9}, {%0,%1,%2,%3};"                \
        : "+f"((c)[0]), "+f"((c)[1]), "+f"((c)[2]), "+f"((c)[3])               \
        : "r"((a)[0]), "r"((a)[1]), "r"((a)[2]), "r"((a)[3]),                  \
          "r"(b0v), "r"(b1v))

__device__ __forceinline__ void split1(float x, __half& h, __half& l) {
    h = __float2half_rn(x);
    l = __float2half_rn(x - __half2float(h));
}

// Dependency-wait: acquire-poll on a global counter until >= target.
__device__ __forceinline__ void wait_ge(int* p, int target) {
    for (;;) {
        int v;
        asm volatile("ld.acquire.gpu.b32 %0, [%1];" : "=r"(v) : "l"(p) : "memory");
        if (v >= target) return;
        __nanosleep(128);
    }
}

// ---------------------------------------------------------------------------
// One 128x128 GEMM tile (R6 inner loop). NT: C[m][n] = sum_k A[m][k]*B[n][k].
// MODE 0: 3-pass, +bias, write half hi/lo. MODE 1: 3-pass, +mask, write fp32.
// MODE 2: 2-pass, write fp32 (Blo unused).
// ---------------------------------------------------------------------------
template <int MODE>
__device__ __forceinline__ void gemm_tile(
    char* smdyn, int bz, int m0, int n0,
    const __half* __restrict__ Ahi, const __half* __restrict__ Alo,
    const __half* __restrict__ Bhi, const __half* __restrict__ Blo,
    size_t sA, size_t sB,
    const float* __restrict__ bias, const float* __restrict__ mask,
    float* __restrict__ outF,
    __half* __restrict__ outHi, __half* __restrict__ outLo)
{
    constexpr bool TWO_PASS = (MODE == 2);
    const int tid  = threadIdx.x;
    const int lane = tid & 31;
    const int wid  = tid >> 5;

    Ahi += (size_t)bz * sA;  Alo += (size_t)bz * sA;
    Bhi += (size_t)bz * sB;
    if (!TWO_PASS) Blo += (size_t)bz * sB;

    const uint32_t sbase = smem_u32(smdyn);

    const int lr = tid >> 1;
    const int c0 = (tid & 1) * 2;
    const uint32_t sw0 = swz((uint32_t)lr, (uint32_t)c0);
    const uint32_t sw1 = swz((uint32_t)lr, (uint32_t)c0 + 1);

    auto load_stage = [&](int c) {
        const uint32_t sb = sbase + (uint32_t)(c % NSTG) * STG_B;
        const size_t kof = (size_t)c * BK + (size_t)c0 * 8;
        const __half* pah = Ahi + (size_t)(m0 + lr) * KDIM + kof;
        const __half* pal = Alo + (size_t)(m0 + lr) * KDIM + kof;
        const __half* pbh = Bhi + (size_t)(n0 + lr) * KDIM + kof;
        cp16(sb + OFF_AH + sw0, pah);
        cp16(sb + OFF_AH + sw1, pah + 8);
        cp16(sb + OFF_AL + sw0, pal);
        cp16(sb + OFF_AL + sw1, pal + 8);
        cp16(sb + OFF_BH + sw0, pbh);
        cp16(sb + OFF_BH + sw1, pbh + 8);
        if (!TWO_PASS) {
            const __half* pbl = Blo + (size_t)(n0 + lr) * KDIM + kof;
            cp16(sb + OFF_BL + sw0, pbl);
            cp16(sb + OFF_BL + sw1, pbl + 8);
        }
    };

    const int wm = (wid & 1) * 64;
    const int wn = (wid >> 1) * 32;
    const uint32_t lrow = (uint32_t)(lane & 15);
    const uint32_t chi  = (uint32_t)(lane >> 4);

    float acc[4][4][4];
    #pragma unroll
    for (int i = 0; i < 4; i++)
        #pragma unroll
        for (int j = 0; j < 4; j++)
            #pragma unroll
            for (int r = 0; r < 4; r++) acc[i][j][r] = 0.0f;

    load_stage(0); CP_COMMIT();
    load_stage(1); CP_COMMIT();

    for (int c = 0; c < NCHUNK; ++c) {
        if (c == NCHUNK - 1) { CP_WAIT(0); } else { CP_WAIT(1); }
        __syncthreads();
        if (c + 2 < NCHUNK) {
            load_stage(c + 2);
            CP_COMMIT();
        }

        const uint32_t sb = sbase + (uint32_t)(c % NSTG) * STG_B;
        #pragma unroll
        for (int ks = 0; ks < 2; ++ks) {
            const uint32_t cseg = (uint32_t)ks * 2 + chi;
            uint32_t ah[4][4], ax[4][4], bh[2][4], bx[2][4];

            #pragma unroll
            for (int smi = 0; smi < 4; ++smi)
                LDSM4(ah[smi], sb + OFF_AH + swz((uint32_t)(wm + smi * 16) + lrow, cseg));
            #pragma unroll
            for (int g = 0; g < 2; ++g)
                LDSM4(bh[g], sb + OFF_BH + swz((uint32_t)(wn + g * 16) + lrow, cseg));
            #pragma unroll
            for (int smi = 0; smi < 4; ++smi)
                #pragma unroll
                for (int sn = 0; sn < 4; ++sn) {
                    const int g = sn >> 1, s = sn & 1;
                    MMA16816(acc[smi][sn], ah[smi], bh[g][s], bh[g][s + 2]);
                }

            #pragma unroll
            for (int smi = 0; smi < 4; ++smi)
                LDSM4(ax[smi], sb + OFF_AL + swz((uint32_t)(wm + smi * 16) + lrow, cseg));
            #pragma unroll
            for (int smi = 0; smi < 4; ++smi)
                #pragma unroll
                for (int sn = 0; sn < 4; ++sn) {
                    const int g = sn >> 1, s = sn & 1;
                    MMA16816(acc[smi][sn], ax[smi], bh[g][s], bh[g][s + 2]);
                }

            if (!TWO_PASS) {
                #pragma unroll
                for (int g = 0; g < 2; ++g)
                    LDSM4(bx[g], sb + OFF_BL + swz((uint32_t)(wn + g * 16) + lrow, cseg));
                #pragma unroll
                for (int smi = 0; smi < 4; ++smi)
                    #pragma unroll
                    for (int sn = 0; sn < 4; ++sn) {
                        const int g = sn >> 1, s = sn & 1;
                        MMA16816(acc[smi][sn], ah[smi], bx[g][s], bx[g][s + 2]);
                    }
            }
        }
    }

    #pragma unroll
    for (int smi = 0; smi < 4; ++smi) {
        const int gm0 = m0 + wm + smi * 16 + (lane >> 2);
        #pragma unroll
        for (int hr = 0; hr < 2; ++hr) {
            const int gm = gm0 + hr * 8;
            #pragma unroll
            for (int sn = 0; sn < 4; ++sn) {
                const int gn = n0 + wn + sn * 8 + 2 * (lane & 3);
                float v0 = acc[smi][sn][hr * 2 + 0];
                float v1 = acc[smi][sn][hr * 2 + 1];
                if (MODE == 0) {
                    v0 += bias[gn]; v1 += bias[gn + 1];
                    __half h0, h1, l0, l1;
                    split1(v0, h0, l0); split1(v1, h1, l1);
                    const size_t off = (size_t)bz * PB + (size_t)gm * 1024 + gn;
                    *reinterpret_cast<__half2*>(outHi + off) = __halves2half2(h0, h1);
                    *reinterpret_cast<__half2*>(outLo + off) = __halves2half2(l0, l1);
                } else if (MODE == 1) {
                    const size_t moff = (size_t)bz * PB + (size_t)gm * 1024 + gn;
                    const float2 mk = *reinterpret_cast<const float2*>(&mask[moff]);
                    v0 += mk.x; v1 += mk.y;
                    float2 o; o.x = v0; o.y = v1;
                    *reinterpret_cast<float2*>(&outF[moff]) = o;
                } else {
                    const size_t off = (size_t)bz * PB + (size_t)gm * 1024 + gn;
                    float2 o; o.x = v0; o.y = v1;
                    *reinterpret_cast<float2*>(&outF[off]) = o;
                }
            }
        }
    }
}

// ---------------------------------------------------------------------------
// Softmax over one (batch, row-block): 128 rows of length 1024. fp32 -> hi/lo.
// ---------------------------------------------------------------------------
__device__ __forceinline__ void softmax_block(
    int bz, int mb,
    const float* __restrict__ score,
    __half* __restrict__ phi, __half* __restrict__ plo)
{
    __shared__ float red[8];
    const int tid = threadIdx.x, lane = tid & 31, wid = tid >> 5;
    const size_t base = (size_t)bz * PB + (size_t)mb * 128 * 1024;

    for (int r = 0; r < 128; ++r) {
        __syncthreads();                 // protect red[] reuse across rows
        const float* p = score + base + (size_t)r * 1024;
        float v[4];
        float mx = -INFINITY;
        #pragma unroll
        for (int i = 0; i < 4; i++) {
            v[i] = __ldcg(p + tid + i * 256);
            mx = fmaxf(mx, v[i]);
        }
        #pragma unroll
        for (int off = 16; off > 0; off >>= 1)
            mx = fmaxf(mx, __shfl_xor_sync(0xffffffffu, mx, off));
        if (lane == 0) red[wid] = mx;
        __syncthreads();
        {
            float m = red[lane & 7];
            #pragma unroll
            for (int off = 4; off > 0; off >>= 1)
                m = fmaxf(m, __shfl_xor_sync(0xffffffffu, m, off));
            mx = m;
        }
        float s = 0.0f;
        #pragma unroll
        for (int i = 0; i < 4; i++) { v[i] = expf(v[i] - mx); s += v[i]; }
        #pragma unroll
        for (int off = 16; off > 0; off >>= 1)
            s += __shfl_xor_sync(0xffffffffu, s, off);
        __syncthreads();
        if (lane == 0) red[wid] = s;
        __syncthreads();
        {
            float t2 = red[lane & 7];
            #pragma unroll
            for (int off = 4; off > 0; off >>= 1)
                t2 += __shfl_xor_sync(0xffffffffu, t2, off);
            s = t2;
        }
        const float inv = 1.0f / s;
        #pragma unroll
        for (int i = 0; i < 4; i++) {
            const float pv = v[i] * inv;
            __half h, l; split1(pv, h, l);
            const size_t o = base + (size_t)r * 1024 + tid + i * 256;
            phi[o] = h;
            plo[o] = l;
        }
    }
}

// ---------------------------------------------------------------------------
// Persistent mega-kernel: dynamic task graph over G1 / G2 / softmax / G3.
// ---------------------------------------------------------------------------
__global__ __launch_bounds__(256, 2) void mega_kernel(
    const __half* __restrict__ Shi, const __half* __restrict__ Slo,
    const __half* __restrict__ Whi, const __half* __restrict__ Wlo,
    const __half* __restrict__ Hhi, const __half* __restrict__ Hlo,
    const __half* __restrict__ Thi,
    __half* __restrict__ SPhi, __half* __restrict__ SPlo,
    float* __restrict__ score,
    __half* __restrict__ Phi, __half* __restrict__ Plo,
    const float* __restrict__ Wb, const float* __restrict__ mask,
    float* __restrict__ out)
{
    extern __shared__ char smdyn[];
    __shared__ int s_task;
    const int tid = threadIdx.x;

    for (;;) {
        __syncthreads();                           // retire prior reads of s_task
        if (tid == 0) s_task = atomicAdd(&g_task, 1);
        __syncthreads();
        const int t = s_task;
        if (t >= NTASK) return;

        if (t < T_G2_0) {
            const int u = t;
            const int bz = u >> 6, mb = (u >> 3) & 7, nb = u & 7;
            gemm_tile<0>(smdyn, bz, mb * 128, nb * 128,
                         Shi, Slo, Whi, Wlo, PB, 0,
                         Wb, nullptr, nullptr, SPhi, SPlo);
            __threadfence(); __syncthreads();
            if (tid == 0) atomicAdd(&g_g1cnt[bz * 8 + mb], 1);
        } else if (t < T_SM_0) {
            const int u = t - T_G2_0;
            const int bz = u >> 6, mb = (u >> 3) & 7, nb = u & 7;
            if (tid == 0) wait_ge(&g_g1cnt[bz * 8 + mb], 8);
            __syncthreads();
            gemm_tile<1>(smdyn, bz, mb * 128, nb * 128,
                         SPhi, SPlo, Hhi, Hlo, PB, PB,
                         nullptr, mask, score, nullptr, nullptr);
            __threadfence(); __syncthreads();
            if (tid == 0) atomicAdd(&g_g2cnt[bz * 8 + mb], 1);
        } else if (t < T_G3_0) {
            const int u = t - T_SM_0;
            const int bz = u >> 3, mb = u & 7;
            if (tid == 0) wait_ge(&g_g2cnt[bz * 8 + mb], 8);
            __syncthreads();
            softmax_block(bz, mb, score, Phi, Plo);
            __threadfence(); __syncthreads();
            if (tid == 0) atomicAdd(&g_smflag[bz * 8 + mb], 1);
        } else {
            const int u = t - T_G3_0;
            const int bz = u >> 6, mb = (u >> 3) & 7, nb = u & 7;
            if (tid == 0) wait_ge(&g_smflag[bz * 8 + mb], 1);
            __syncthreads();
            gemm_tile<2>(smdyn, bz, mb * 128, nb * 128,
                         Phi, Plo, Thi, nullptr, PB, PB,
                         nullptr, nullptr, out, nullptr, nullptr);
        }
    }
}

// ---------------------------------------------------------------------------
// Counter init (runs each launch, before mega_kernel)
// ---------------------------------------------------------------------------
__global__ void init_counters()
{
    const int i = threadIdx.x;
    if (i == 0) g_task = 0;
    if (i < Bn * 8) {
        g_g1cnt[i] = 0;
        g_g2cnt[i] = 0;
        g_smflag[i] = 0;
    }
}

// ---------------------------------------------------------------------------
// fp32 -> fp16 hi/lo split (elementwise)
// ---------------------------------------------------------------------------
__global__ __launch_bounds__(256) void split_plain(
    const float* __restrict__ x, __half* __restrict__ hi,
    __half* __restrict__ lo, size_t n)
{
    const size_t i = ((size_t)blockIdx.x * 256 + threadIdx.x) * 4;
    if (i >= n) return;
    const float4 v = *reinterpret_cast<const float4*>(&x[i]);
    __half h0, h1, h2, h3, l0, l1, l2, l3;
    split1(v.x, h0, l0); split1(v.y, h1, l1);
    split1(v.z, h2, l2); split1(v.w, h3, l3);
    __half2 hv[2] = { __halves2half2(h0, h1), __halves2half2(h2, h3) };
    __half2 lv[2] = { __halves2half2(l0, l1), __halves2half2(l2, l3) };
    *reinterpret_cast<uint2*>(hi + i) = *reinterpret_cast<uint2*>(hv);
    *reinterpret_cast<uint2*>(lo + i) = *reinterpret_cast<uint2*>(lv);
}

// ---------------------------------------------------------------------------
// H: split to hi/lo AND transposed hi ([B][D2][LH])
// ---------------------------------------------------------------------------
__global__ __launch_bounds__(256) void split_h(
    const float* __restrict__ H,
    __half* __restrict__ Hhi, __half* __restrict__ Hlo,
    __half* __restrict__ Thi)
{
    __shared__ float tile[32][33];
    const int b = blockIdx.z;
    const int t0 = blockIdx.y * 32;
    const int e0 = blockIdx.x * 32;
    const int tx = threadIdx.x & 31, ty = threadIdx.x >> 5;
    const size_t base = (size_t)b * PB;

    #pragma unroll
    for (int i = 0; i < 4; ++i) {
        const int r = ty + i * 8;
        const float v = H[base + (size_t)(t0 + r) * 1024 + e0 + tx];
        tile[r][tx] = v;
        __half h, l; split1(v, h, l);
        const size_t off = base + (size_t)(t0 + r) * 1024 + e0 + tx;
        Hhi[off] = h; Hlo[off] = l;
    }
    __syncthreads();
    #pragma unroll
    for (int i = 0; i < 4; ++i) {
        const int r = ty + i * 8;
        const float v = tile[tx][r];
        const size_t off = base + (size_t)(e0 + r) * 1024 + t0 + tx;
        Thi[off] = __float2half_rn(v);
    }
}

// ---------------------------------------------------------------------------
// Launch
// ---------------------------------------------------------------------------
extern "C" void kernel_launch(void* const* d_in, const int* in_sizes, int n_in,
                              void* d_out, int out_size)
{
    const float* S    = (const float*)d_in[0];
    const float* H    = (const float*)d_in[1];
    const float* mask = (const float*)d_in[2];
    const float* Ww   = (const float*)d_in[3];
    const float* Wb   = (const float*)d_in[4];
    float* out = (float*)d_out;

    __half *Shi, *Slo, *Whi, *Wlo, *Hhi, *Hlo, *Thi;
    __half *SPhi, *SPlo, *Phi, *Plo;
    float* score;
    cudaGetSymbolAddress((void**)&Shi, g_Shi);   cudaGetSymbolAddress((void**)&Slo, g_Slo);
    cudaGetSymbolAddress((void**)&Whi, g_Whi);   cudaGetSymbolAddress((void**)&Wlo, g_Wlo);
    cudaGetSymbolAddress((void**)&Hhi, g_Hhi);   cudaGetSymbolAddress((void**)&Hlo, g_Hlo);
    cudaGetSymbolAddress((void**)&Thi, g_Thi);
    cudaGetSymbolAddress((void**)&SPhi, g_SPhi); cudaGetSymbolAddress((void**)&SPlo, g_SPlo);
    cudaGetSymbolAddress((void**)&Phi, g_Phi);   cudaGetSymbolAddress((void**)&Plo, g_Plo);
    cudaGetSymbolAddress((void**)&score, g_score);

    cudaFuncSetAttribute(mega_kernel, cudaFuncAttributeMaxDynamicSharedMemorySize, SMEM_BYTES);

    // input splits
    split_plain<<<(unsigned)(ELEMS / 1024), 256>>>(S, Shi, Slo, ELEMS);
    split_plain<<<1024, 256>>>(Ww, Whi, Wlo, (size_t)1024 * 1024);
    split_h<<<dim3(32, 32, Bn), 256>>>(H, Hhi, Hlo, Thi);

    // task-graph state
    init_counters<<<1, 256>>>();

    // fused persistent pipeline: G1 -> G2 -> softmax -> G3
    mega_kernel<<<GRID_P, 256, SMEM_BYTES>>>(
        Shi, Slo, Whi, Wlo, Hhi, Hlo, Thi,
        SPhi, SPlo, score, Phi, Plo,
        Wb, mask, out);
}

// round 12
// speedup vs baseline: 1.0738x; 1.0738x over previous
#include <cuda_runtime.h>
#include <cuda_fp16.h>
#include <math.h>
#include <stdint.h>

// Problem constants
#define Bn    16
#define KDIM  1024
#define PB    ((size_t)1024 * 1024)

// GEMM tiling (R6-proven): CTA tile 128x128, K chunks of 32 halves
#define BK      32
#define NCHUNK  (KDIM / BK)   // 32
#define TILE_B  8192
#define OFF_AH  0
#define OFF_AL  (1 * TILE_B)
#define OFF_BH  (2 * TILE_B)
#define OFF_BL  (3 * TILE_B)
#define STG_B   (4 * TILE_B)          // 32 KB / stage
#define NSTG    3
#define SMEM_BYTES (NSTG * STG_B)     // 96 KB

// Task graph: [G1 1024][G2 1024][SM 1024 x 16 rows][G3 1024]
#define NT_G1   1024
#define NT_G2   1024
#define NT_SM   1024
#define NT_G3   1024
#define T_G2_0  (NT_G1)
#define T_SM_0  (NT_G1 + NT_G2)
#define T_G3_0  (NT_G1 + NT_G2 + NT_SM)
#define NTASK   (NT_G1 + NT_G2 + NT_SM + NT_G3)   // 4096
#define GRID_P  296

// ---------------------------------------------------------------------------
// Device scratch + task-graph state
// ---------------------------------------------------------------------------
#define ELEMS ((size_t)Bn * 1024 * 1024)
__device__ __half g_Shi[ELEMS], g_Slo[ELEMS];
__device__ __half g_Whi[1024 * 1024], g_Wlo[1024 * 1024];
__device__ __half g_Hhi[ELEMS], g_Hlo[ELEMS];
__device__ __half g_Thi[ELEMS];                   // H transposed (hi only)
__device__ __half g_SPhi[ELEMS], g_SPlo[ELEMS];   // G1 out
__device__ __half g_Phi[ELEMS], g_Plo[ELEMS];     // softmax out
__device__ float  g_score[ELEMS];

__device__ int g_task;
__device__ int g_g1cnt[Bn * 8];
__device__ int g_g2cnt[Bn * 8];
__device__ int g_smcnt[Bn * 8];

// ---------------------------------------------------------------------------
// Helpers
// ---------------------------------------------------------------------------
__device__ __forceinline__ uint32_t smem_u32(const void* p) {
    return (uint32_t)__cvta_generic_to_shared(p);
}
__device__ __forceinline__ void cp16(uint32_t dst, const void* src) {
    asm volatile("cp.async.cg.shared.global [%0], [%1], 16;\n"
                 :: "r"(dst), "l"(src) : "memory");
}
#define CP_COMMIT() asm volatile("cp.async.commit_group;\n" ::: "memory")
#define CP_WAIT(n)  asm volatile("cp.async.wait_group %0;\n" :: "n"(n) : "memory")

__device__ __forceinline__ uint32_t swz(uint32_t r, uint32_t c) {
    return (r >> 1) * 128u + (((((r & 1u) << 2) | (c ^ ((r >> 1) & 3u)))) << 4);
}

#define LDSM4(r, a)                                                            \
    asm volatile("ldmatrix.sync.aligned.m8n8.x4.shared.b16 {%0,%1,%2,%3}, [%4];" \
        : "=r"((r)[0]), "=r"((r)[1]), "=r"((r)[2]), "=r"((r)[3]) : "r"(a))

#define MMA16816(c, a, b0v, b1v)                                               \
    asm volatile("mma.sync.aligned.m16n8k16.row.col.f32.f16.f16.f32 "          \
        "{%0,%1,%2,%3}, {%4,%5,%6,%7}, {%8,%9}, {%0,%1,%2,%3};"                \
        : "+f"((c)[0]), "+f"((c)[1]), "+f"((c)[2]), "+f"((c)[3])               \
        : "r"((a)[0]), "r"((a)[1]), "r"((a)[2]), "r"((a)[3]),                  \
          "r"(b0v), "r"(b1v))

__device__ __forceinline__ void split1(float x, __half& h, __half& l) {
    h = __float2half_rn(x);
    l = __float2half_rn(x - __half2float(h));
}

__device__ __forceinline__ void wait_ge(int* p, int target) {
    for (;;) {
        int v;
        asm volatile("ld.acquire.gpu.b32 %0, [%1];" : "=r"(v) : "l"(p) : "memory");
        if (v >= target) return;
        __nanosleep(128);
    }
}

// ---------------------------------------------------------------------------
// One 128x128 GEMM tile (R6 inner loop). NT: C[m][n] = sum_k A[m][k]*B[n][k].
// MODE 0: 3-pass, +bias, write half hi/lo. MODE 1: 3-pass, +mask, write fp32.
// MODE 2: 2-pass, write fp32 (Blo unused).
// ---------------------------------------------------------------------------
template <int MODE>
__device__ __forceinline__ void gemm_tile(
    char* smdyn, int bz, int m0, int n0,
    const __half* __restrict__ Ahi, const __half* __restrict__ Alo,
    const __half* __restrict__ Bhi, const __half* __restrict__ Blo,
    size_t sA, size_t sB,
    const float* __restrict__ bias, const float* __restrict__ mask,
    float* __restrict__ outF,
    __half* __restrict__ outHi, __half* __restrict__ outLo)
{
    constexpr bool TWO_PASS = (MODE == 2);
    const int tid  = threadIdx.x;
    const int lane = tid & 31;
    const int wid  = tid >> 5;

    Ahi += (size_t)bz * sA;  Alo += (size_t)bz * sA;
    Bhi += (size_t)bz * sB;
    if (!TWO_PASS) Blo += (size_t)bz * sB;

    const uint32_t sbase = smem_u32(smdyn);

    const int lr = tid >> 1;
    const int c0 = (tid & 1) * 2;
    const uint32_t sw0 = swz((uint32_t)lr, (uint32_t)c0);
    const uint32_t sw1 = swz((uint32_t)lr, (uint32_t)c0 + 1);

    auto load_stage = [&](int c) {
        const uint32_t sb = sbase + (uint32_t)(c % NSTG) * STG_B;
        const size_t kof = (size_t)c * BK + (size_t)c0 * 8;
        const __half* pah = Ahi + (size_t)(m0 + lr) * KDIM + kof;
        const __half* pal = Alo + (size_t)(m0 + lr) * KDIM + kof;
        const __half* pbh = Bhi + (size_t)(n0 + lr) * KDIM + kof;
        cp16(sb + OFF_AH + sw0, pah);
        cp16(sb + OFF_AH + sw1, pah + 8);
        cp16(sb + OFF_AL + sw0, pal);
        cp16(sb + OFF_AL + sw1, pal + 8);
        cp16(sb + OFF_BH + sw0, pbh);
        cp16(sb + OFF_BH + sw1, pbh + 8);
        if (!TWO_PASS) {
            const __half* pbl = Blo + (size_t)(n0 + lr) * KDIM + kof;
            cp16(sb + OFF_BL + sw0, pbl);
            cp16(sb + OFF_BL + sw1, pbl + 8);
        }
    };

    const int wm = (wid & 1) * 64;
    const int wn = (wid >> 1) * 32;
    const uint32_t lrow = (uint32_t)(lane & 15);
    const uint32_t chi  = (uint32_t)(lane >> 4);

    float acc[4][4][4];
    #pragma unroll
    for (int i = 0; i < 4; i++)
        #pragma unroll
        for (int j = 0; j < 4; j++)
            #pragma unroll
            for (int r = 0; r < 4; r++) acc[i][j][r] = 0.0f;

    load_stage(0); CP_COMMIT();
    load_stage(1); CP_COMMIT();

    for (int c = 0; c < NCHUNK; ++c) {
        if (c == NCHUNK - 1) { CP_WAIT(0); } else { CP_WAIT(1); }
        __syncthreads();
        if (c + 2 < NCHUNK) {
            load_stage(c + 2);
            CP_COMMIT();
        }

        const uint32_t sb = sbase + (uint32_t)(c % NSTG) * STG_B;
        #pragma unroll
        for (int ks = 0; ks < 2; ++ks) {
            const uint32_t cseg = (uint32_t)ks * 2 + chi;
            uint32_t ah[4][4], ax[4][4], bh[2][4], bx[2][4];

            #pragma unroll
            for (int smi = 0; smi < 4; ++smi)
                LDSM4(ah[smi], sb + OFF_AH + swz((uint32_t)(wm + smi * 16) + lrow, cseg));
            #pragma unroll
            for (int g = 0; g < 2; ++g)
                LDSM4(bh[g], sb + OFF_BH + swz((uint32_t)(wn + g * 16) + lrow, cseg));
            #pragma unroll
            for (int smi = 0; smi < 4; ++smi)
                #pragma unroll
                for (int sn = 0; sn < 4; ++sn) {
                    const int g = sn >> 1, s = sn & 1;
                    MMA16816(acc[smi][sn], ah[smi], bh[g][s], bh[g][s + 2]);
                }

            #pragma unroll
            for (int smi = 0; smi < 4; ++smi)
                LDSM4(ax[smi], sb + OFF_AL + swz((uint32_t)(wm + smi * 16) + lrow, cseg));
            #pragma unroll
            for (int smi = 0; smi < 4; ++smi)
                #pragma unroll
                for (int sn = 0; sn < 4; ++sn) {
                    const int g = sn >> 1, s = sn & 1;
                    MMA16816(acc[smi][sn], ax[smi], bh[g][s], bh[g][s + 2]);
                }

            if (!TWO_PASS) {
                #pragma unroll
                for (int g = 0; g < 2; ++g)
                    LDSM4(bx[g], sb + OFF_BL + swz((uint32_t)(wn + g * 16) + lrow, cseg));
                #pragma unroll
                for (int smi = 0; smi < 4; ++smi)
                    #pragma unroll
                    for (int sn = 0; sn < 4; ++sn) {
                        const int g = sn >> 1, s = sn & 1;
                        MMA16816(acc[smi][sn], ah[smi], bx[g][s], bx[g][s + 2]);
                    }
            }
        }
    }

    #pragma unroll
    for (int smi = 0; smi < 4; ++smi) {
        const int gm0 = m0 + wm + smi * 16 + (lane >> 2);
        #pragma unroll
        for (int hr = 0; hr < 2; ++hr) {
            const int gm = gm0 + hr * 8;
            #pragma unroll
            for (int sn = 0; sn < 4; ++sn) {
                const int gn = n0 + wn + sn * 8 + 2 * (lane & 3);
                float v0 = acc[smi][sn][hr * 2 + 0];
                float v1 = acc[smi][sn][hr * 2 + 1];
                if (MODE == 0) {
                    v0 += bias[gn]; v1 += bias[gn + 1];
                    __half h0, h1, l0, l1;
                    split1(v0, h0, l0); split1(v1, h1, l1);
                    const size_t off = (size_t)bz * PB + (size_t)gm * 1024 + gn;
                    *reinterpret_cast<__half2*>(outHi + off) = __halves2half2(h0, h1);
                    *reinterpret_cast<__half2*>(outLo + off) = __halves2half2(l0, l1);
                } else if (MODE == 1) {
                    const size_t moff = (size_t)bz * PB + (size_t)gm * 1024 + gn;
                    const float2 mk = *reinterpret_cast<const float2*>(&mask[moff]);
                    v0 += mk.x; v1 += mk.y;
                    float2 o; o.x = v0; o.y = v1;
                    *reinterpret_cast<float2*>(&outF[moff]) = o;
                } else {
                    const size_t off = (size_t)bz * PB + (size_t)gm * 1024 + gn;
                    float2 o; o.x = v0; o.y = v1;
                    *reinterpret_cast<float2*>(&outF[off]) = o;
                }
            }
        }
    }
}

// ---------------------------------------------------------------------------
// Softmax task: 16 rows, warp-per-row (8 warps x 2 rounds), no block barriers.
// Each lane owns a contiguous 32-float segment of its row.
// ---------------------------------------------------------------------------
__device__ __forceinline__ void softmax16(
    int bz, int rb,
    const float* __restrict__ score,
    __half* __restrict__ phi, __half* __restrict__ plo)
{
    const int lane = threadIdx.x & 31;
    const int wid  = threadIdx.x >> 5;

    #pragma unroll
    for (int round = 0; round < 2; ++round) {
        const int row = rb * 16 + round * 8 + wid;
        const size_t base = (size_t)bz * PB + (size_t)row * 1024 + (size_t)lane * 32;
        const float4* p4 = reinterpret_cast<const float4*>(score + base);

        float v[32];
        #pragma unroll
        for (int i = 0; i < 8; ++i) {
            const float4 t = __ldcg(p4 + i);
            v[i * 4 + 0] = t.x; v[i * 4 + 1] = t.y;
            v[i * 4 + 2] = t.z; v[i * 4 + 3] = t.w;
        }
        float mx = v[0];
        #pragma unroll
        for (int i = 1; i < 32; ++i) mx = fmaxf(mx, v[i]);
        #pragma unroll
        for (int off = 16; off > 0; off >>= 1)
            mx = fmaxf(mx, __shfl_xor_sync(0xffffffffu, mx, off));
        float s = 0.0f;
        #pragma unroll
        for (int i = 0; i < 32; ++i) { v[i] = expf(v[i] - mx); s += v[i]; }
        #pragma unroll
        for (int off = 16; off > 0; off >>= 1)
            s += __shfl_xor_sync(0xffffffffu, s, off);
        const float inv = 1.0f / s;

        uint32_t hw[16], lw[16];
        #pragma unroll
        for (int i = 0; i < 16; ++i) {
            const float a = v[2 * i] * inv, b = v[2 * i + 1] * inv;
            __half ha, la, hb, lb;
            split1(a, ha, la); split1(b, hb, lb);
            __half2 hh = __halves2half2(ha, hb);
            __half2 ll = __halves2half2(la, lb);
            hw[i] = *reinterpret_cast<uint32_t*>(&hh);
            lw[i] = *reinterpret_cast<uint32_t*>(&ll);
        }
        uint4* ph = reinterpret_cast<uint4*>(phi + base);
        uint4* pl = reinterpret_cast<uint4*>(plo + base);
        #pragma unroll
        for (int i = 0; i < 4; ++i) {
            uint4 a; a.x = hw[4*i]; a.y = hw[4*i+1]; a.z = hw[4*i+2]; a.w = hw[4*i+3];
            uint4 b; b.x = lw[4*i]; b.y = lw[4*i+1]; b.z = lw[4*i+2]; b.w = lw[4*i+3];
            ph[i] = a;
            pl[i] = b;
        }
    }
}

// ---------------------------------------------------------------------------
// Persistent mega-kernel
// ---------------------------------------------------------------------------
__global__ __launch_bounds__(256, 2) void mega_kernel(
    const __half* __restrict__ Shi, const __half* __restrict__ Slo,
    const __half* __restrict__ Whi, const __half* __restrict__ Wlo,
    const __half* __restrict__ Hhi, const __half* __restrict__ Hlo,
    const __half* __restrict__ Thi,
    __half* __restrict__ SPhi, __half* __restrict__ SPlo,
    float* __restrict__ score,
    __half* __restrict__ Phi, __half* __restrict__ Plo,
    const float* __restrict__ Wb, const float* __restrict__ mask,
    float* __restrict__ out)
{
    extern __shared__ char smdyn[];
    __shared__ int s_task;
    const int tid = threadIdx.x;

    for (;;) {
        __syncthreads();
        if (tid == 0) s_task = atomicAdd(&g_task, 1);
        __syncthreads();
        const int t = s_task;
        if (t >= NTASK) return;

        if (t < T_G2_0) {
            const int u = t;
            const int bz = u >> 6, mb = (u >> 3) & 7, nb = u & 7;
            gemm_tile<0>(smdyn, bz, mb * 128, nb * 128,
                         Shi, Slo, Whi, Wlo, PB, 0,
                         Wb, nullptr, nullptr, SPhi, SPlo);
            __threadfence(); __syncthreads();
            if (tid == 0) atomicAdd(&g_g1cnt[bz * 8 + mb], 1);
        } else if (t < T_SM_0) {
            const int u = t - T_G2_0;
            const int bz = u >> 6, mb = (u >> 3) & 7, nb = u & 7;
            if (tid == 0) wait_ge(&g_g1cnt[bz * 8 + mb], 8);
            __syncthreads();
            gemm_tile<1>(smdyn, bz, mb * 128, nb * 128,
                         SPhi, SPlo, Hhi, Hlo, PB, PB,
                         nullptr, mask, score, nullptr, nullptr);
            __threadfence(); __syncthreads();
            if (tid == 0) atomicAdd(&g_g2cnt[bz * 8 + mb], 1);
        } else if (t < T_G3_0) {
            const int u = t - T_SM_0;
            const int bz = u >> 6, rb = u & 63;   // 16 rows per task
            const int mb = rb >> 3;
            if (tid == 0) wait_ge(&g_g2cnt[bz * 8 + mb], 8);
            __syncthreads();
            softmax16(bz, rb, score, Phi, Plo);
            __threadfence(); __syncthreads();
            if (tid == 0) atomicAdd(&g_smcnt[bz * 8 + mb], 1);
        } else {
            const int u = t - T_G3_0;
            const int bz = u >> 6, mb = (u >> 3) & 7, nb = u & 7;
            if (tid == 0) wait_ge(&g_smcnt[bz * 8 + mb], 8);
            __syncthreads();
            gemm_tile<2>(smdyn, bz, mb * 128, nb * 128,
                         Phi, Plo, Thi, nullptr, PB, PB,
                         nullptr, nullptr, out, nullptr, nullptr);
        }
    }
}

// ---------------------------------------------------------------------------
// fp32 -> fp16 hi/lo split (elementwise)
// ---------------------------------------------------------------------------
__global__ __launch_bounds__(256) void split_plain(
    const float* __restrict__ x, __half* __restrict__ hi,
    __half* __restrict__ lo, size_t n)
{
    const size_t i = ((size_t)blockIdx.x * 256 + threadIdx.x) * 4;
    if (i >= n) return;
    const float4 v = *reinterpret_cast<const float4*>(&x[i]);
    __half h0, h1, h2, h3, l0, l1, l2, l3;
    split1(v.x, h0, l0); split1(v.y, h1, l1);
    split1(v.z, h2, l2); split1(v.w, h3, l3);
    __half2 hv[2] = { __halves2half2(h0, h1), __halves2half2(h2, h3) };
    __half2 lv[2] = { __halves2half2(l0, l1), __halves2half2(l2, l3) };
    *reinterpret_cast<uint2*>(hi + i) = *reinterpret_cast<uint2*>(hv);
    *reinterpret_cast<uint2*>(lo + i) = *reinterpret_cast<uint2*>(lv);
}

// ---------------------------------------------------------------------------
// H: split to hi/lo AND transposed hi ([B][D2][LH]); block (0,0,0) also
// zeroes the task-graph counters (runs before mega_kernel in stream order).
// ---------------------------------------------------------------------------
__global__ __launch_bounds__(256) void split_h(
    const float* __restrict__ H,
    __half* __restrict__ Hhi, __half* __restrict__ Hlo,
    __half* __restrict__ Thi)
{
    __shared__ float tile[32][33];
    const int b = blockIdx.z;
    const int t0 = blockIdx.y * 32;
    const int e0 = blockIdx.x * 32;
    const int tx = threadIdx.x & 31, ty = threadIdx.x >> 5;
    const size_t base = (size_t)b * PB;

    if (blockIdx.x == 0 && blockIdx.y == 0 && blockIdx.z == 0) {
        const int i = threadIdx.x;
        if (i == 0) g_task = 0;
        if (i < Bn * 8) {
            g_g1cnt[i] = 0;
            g_g2cnt[i] = 0;
            g_smcnt[i] = 0;
        }
    }

    #pragma unroll
    for (int i = 0; i < 4; ++i) {
        const int r = ty + i * 8;
        const float v = H[base + (size_t)(t0 + r) * 1024 + e0 + tx];
        tile[r][tx] = v;
        __half h, l; split1(v, h, l);
        const size_t off = base + (size_t)(t0 + r) * 1024 + e0 + tx;
        Hhi[off] = h; Hlo[off] = l;
    }
    __syncthreads();
    #pragma unroll
    for (int i = 0; i < 4; ++i) {
        const int r = ty + i * 8;
        const float v = tile[tx][r];
        const size_t off = base + (size_t)(e0 + r) * 1024 + t0 + tx;
        Thi[off] = __float2half_rn(v);
    }
}

// ---------------------------------------------------------------------------
// Launch
// ---------------------------------------------------------------------------
extern "C" void kernel_launch(void* const* d_in, const int* in_sizes, int n_in,
                              void* d_out, int out_size)
{
    const float* S    = (const float*)d_in[0];
    const float* H    = (const float*)d_in[1];
    const float* mask = (const float*)d_in[2];
    const float* Ww   = (const float*)d_in[3];
    const float* Wb   = (const float*)d_in[4];
    float* out = (float*)d_out;

    __half *Shi, *Slo, *Whi, *Wlo, *Hhi, *Hlo, *Thi;
    __half *SPhi, *SPlo, *Phi, *Plo;
    float* score;
    cudaGetSymbolAddress((void**)&Shi, g_Shi);   cudaGetSymbolAddress((void**)&Slo, g_Slo);
    cudaGetSymbolAddress((void**)&Whi, g_Whi);   cudaGetSymbolAddress((void**)&Wlo, g_Wlo);
    cudaGetSymbolAddress((void**)&Hhi, g_Hhi);   cudaGetSymbolAddress((void**)&Hlo, g_Hlo);
    cudaGetSymbolAddress((void**)&Thi, g_Thi);
    cudaGetSymbolAddress((void**)&SPhi, g_SPhi); cudaGetSymbolAddress((void**)&SPlo, g_SPlo);
    cudaGetSymbolAddress((void**)&Phi, g_Phi);   cudaGetSymbolAddress((void**)&Plo, g_Plo);
    cudaGetSymbolAddress((void**)&score, g_score);

    cudaFuncSetAttribute(mega_kernel, cudaFuncAttributeMaxDynamicSharedMemorySize, SMEM_BYTES);

    // input splits (+ counter init inside split_h block 0)
    split_plain<<<(unsigned)(ELEMS / 1024), 256>>>(S, Shi, Slo, ELEMS);
    split_plain<<<1024, 256>>>(Ww, Whi, Wlo, (size_t)1024 * 1024);
    split_h<<<dim3(32, 32, Bn), 256>>>(H, Hhi, Hlo, Thi);

    // fused persistent pipeline: G1 -> G2 -> softmax -> G3
    mega_kernel<<<GRID_P, 256, SMEM_BYTES>>>(
        Shi, Slo, Whi, Wlo, Hhi, Hlo, Thi,
        SPhi, SPlo, score, Phi, Plo,
        Wb, mask, out);
}

// round 13
// speedup vs baseline: 1.2561x; 1.1698x over previous
#include <cuda_runtime.h>
#include <cuda_fp16.h>
#include <math.h>
#include <stdint.h>

// Problem constants
#define Bn    16
#define KDIM  1024
#define PB    ((size_t)1024 * 1024)

// GEMM tiling
#define BK      32            // halves per K chunk (64B per row)
#define NCHUNK  (KDIM / BK)   // 32
#define TILE_B  8192          // bytes per 128x32-half tile (swizzled, no pad)
#define OFF_AH  0
#define OFF_AL  (1 * TILE_B)
#define OFF_BH  (2 * TILE_B)
#define OFF_BL  (3 * TILE_B)
#define STG_B   (4 * TILE_B)          // 32 KB / stage
#define NSTG    3
#define SMEM_BYTES (NSTG * STG_B)     // 96 KB

// ---------------------------------------------------------------------------
// Device scratch (device globals: allowed)
// ---------------------------------------------------------------------------
#define ELEMS ((size_t)Bn * 1024 * 1024)
__device__ __half g_Shi[ELEMS], g_Slo[ELEMS];
__device__ __half g_Whi[1024 * 1024], g_Wlo[1024 * 1024];
__device__ __half g_Hhi[ELEMS], g_Hlo[ELEMS];
__device__ __half g_Thi[ELEMS];                   // H transposed (hi only)
__device__ __half g_SPhi[ELEMS], g_SPlo[ELEMS];   // GEMM1 out
__device__ __half g_Phi[ELEMS];                   // softmax out (hi only)
__device__ float  g_score[ELEMS];

// ---------------------------------------------------------------------------
// Helpers
// ---------------------------------------------------------------------------
__device__ __forceinline__ uint32_t smem_u32(const void* p) {
    return (uint32_t)__cvta_generic_to_shared(p);
}
__device__ __forceinline__ void cp16(uint32_t dst, const void* src) {
    asm volatile("cp.async.cg.shared.global [%0], [%1], 16;\n"
                 :: "r"(dst), "l"(src) : "memory");
}
#define CP_COMMIT() asm volatile("cp.async.commit_group;\n" ::: "memory")
#define CP_WAIT(n)  asm volatile("cp.async.wait_group %0;\n" :: "n"(n) : "memory")

// Swizzled byte offset within a (rows x 32-half) tile (rows of 64B packed).
__device__ __forceinline__ uint32_t swz(uint32_t r, uint32_t c) {
    return (r >> 1) * 128u + (((((r & 1u) << 2) | (c ^ ((r >> 1) & 3u)))) << 4);
}

#define LDSM4(r, a)                                                            \
    asm volatile("ldmatrix.sync.aligned.m8n8.x4.shared.b16 {%0,%1,%2,%3}, [%4];" \
        : "=r"((r)[0]), "=r"((r)[1]), "=r"((r)[2]), "=r"((r)[3]) : "r"(a))

#define MMA16816(c, a, b0v, b1v)                                               \
    asm volatile("mma.sync.aligned.m16n8k16.row.col.f32.f16.f16.f32 "          \
        "{%0,%1,%2,%3}, {%4,%5,%6,%7}, {%8,%9}, {%0,%1,%2,%3};"                \
        : "+f"((c)[0]), "+f"((c)[1]), "+f"((c)[2]), "+f"((c)[3])               \
        : "r"((a)[0]), "r"((a)[1]), "r"((a)[2]), "r"((a)[3]),                  \
          "r"(b0v), "r"(b1v))

__device__ __forceinline__ void split1(float x, __half& h, __half& l) {
    h = __float2half_rn(x);
    l = __float2half_rn(x - __half2float(h));
}

// ---------------------------------------------------------------------------
// HMMA NT GEMM (C[m][n] = sum_k A[m][k]*B[n][k]), fp16 hi/lo split, f32 acc.
// 3-stage cp.async pipeline, 1 barrier per K chunk, 2 CTAs/SM.
// MODE 0: 3-pass (hh + al*bh + ah*bl), +bias[n], write __half hi/lo.
// MODE 1: 3-pass, +mask, write fp32.
// MODE 2: 1-pass (hh only), write fp32. Alo/Blo unused.
// ---------------------------------------------------------------------------
template <int MODE>
__global__ __launch_bounds__(256, 2) void gemm3x(
    const __half* __restrict__ Ahi, const __half* __restrict__ Alo,
    const __half* __restrict__ Bhi, const __half* __restrict__ Blo,
    size_t sA, size_t sB,
    const float* __restrict__ bias,
    const float* __restrict__ mask, size_t sMask,
    float* __restrict__ outF, size_t sOutF,
    __half* __restrict__ outHi, __half* __restrict__ outLo, size_t sOutB)
{
    constexpr bool ONE_PASS = (MODE == 2);
    extern __shared__ __half sm[];

    const int tid  = threadIdx.x;
    const int lane = tid & 31;
    const int wid  = tid >> 5;
    const int m0 = blockIdx.y * 128, n0 = blockIdx.x * 128, bz = blockIdx.z;

    Ahi += (size_t)bz * sA;
    Bhi += (size_t)bz * sB;
    if (!ONE_PASS) { Alo += (size_t)bz * sA; Blo += (size_t)bz * sB; }

    const uint32_t sbase = smem_u32(sm);

    // --- gmem->smem loader mapping: thread -> (row, 2x16B segs) per tile
    const int lr = tid >> 1;                 // 0..127
    const int c0 = (tid & 1) * 2;            // seg 0 or 2
    const uint32_t sw0 = swz((uint32_t)lr, (uint32_t)c0);
    const uint32_t sw1 = swz((uint32_t)lr, (uint32_t)c0 + 1);

    auto load_stage = [&](int c) {
        const uint32_t sb = sbase + (uint32_t)(c % NSTG) * STG_B;
        const size_t kof = (size_t)c * BK + (size_t)c0 * 8;
        const __half* pah = Ahi + (size_t)(m0 + lr) * KDIM + kof;
        const __half* pbh = Bhi + (size_t)(n0 + lr) * KDIM + kof;
        cp16(sb + OFF_AH + sw0, pah);
        cp16(sb + OFF_AH + sw1, pah + 8);
        cp16(sb + OFF_BH + sw0, pbh);
        cp16(sb + OFF_BH + sw1, pbh + 8);
        if (!ONE_PASS) {
            const __half* pal = Alo + (size_t)(m0 + lr) * KDIM + kof;
            const __half* pbl = Blo + (size_t)(n0 + lr) * KDIM + kof;
            cp16(sb + OFF_AL + sw0, pal);
            cp16(sb + OFF_AL + sw1, pal + 8);
            cp16(sb + OFF_BL + sw0, pbl);
            cp16(sb + OFF_BL + sw1, pbl + 8);
        }
    };

    // --- per-warp compute mapping: warp tile 64(M) x 32(N)
    const int wm = (wid & 1) * 64;
    const int wn = (wid >> 1) * 32;
    const uint32_t lrow = (uint32_t)(lane & 15);
    const uint32_t chi  = (uint32_t)(lane >> 4);

    float acc[4][4][4];
    #pragma unroll
    for (int i = 0; i < 4; i++)
        #pragma unroll
        for (int j = 0; j < 4; j++)
            #pragma unroll
            for (int r = 0; r < 4; r++) acc[i][j][r] = 0.0f;

    // Prologue: stages 0, 1
    load_stage(0); CP_COMMIT();
    load_stage(1); CP_COMMIT();

    for (int c = 0; c < NCHUNK; ++c) {
        if (c == NCHUNK - 1) { CP_WAIT(0); } else { CP_WAIT(1); }
        __syncthreads();  // stage c visible; retires compute(c-1)
        if (c + 2 < NCHUNK) {
            load_stage(c + 2);
            CP_COMMIT();
        }

        const uint32_t sb = sbase + (uint32_t)(c % NSTG) * STG_B;
        #pragma unroll
        for (int ks = 0; ks < 2; ++ks) {
            const uint32_t cseg = (uint32_t)ks * 2 + chi;
            uint32_t ah[4][4], ax[4][4], bh[2][4], bx[2][4];

            // --- pass 1: hi * hi
            #pragma unroll
            for (int smi = 0; smi < 4; ++smi)
                LDSM4(ah[smi], sb + OFF_AH + swz((uint32_t)(wm + smi * 16) + lrow, cseg));
            #pragma unroll
            for (int g = 0; g < 2; ++g)
                LDSM4(bh[g], sb + OFF_BH + swz((uint32_t)(wn + g * 16) + lrow, cseg));
            #pragma unroll
            for (int smi = 0; smi < 4; ++smi)
                #pragma unroll
                for (int sn = 0; sn < 4; ++sn) {
                    const int g = sn >> 1, s = sn & 1;
                    MMA16816(acc[smi][sn], ah[smi], bh[g][s], bh[g][s + 2]);
                }

            if (!ONE_PASS) {
                // --- pass 2: lo_A * hi_B
                #pragma unroll
                for (int smi = 0; smi < 4; ++smi)
                    LDSM4(ax[smi], sb + OFF_AL + swz((uint32_t)(wm + smi * 16) + lrow, cseg));
                #pragma unroll
                for (int smi = 0; smi < 4; ++smi)
                    #pragma unroll
                    for (int sn = 0; sn < 4; ++sn) {
                        const int g = sn >> 1, s = sn & 1;
                        MMA16816(acc[smi][sn], ax[smi], bh[g][s], bh[g][s + 2]);
                    }

                // --- pass 3: hi_A * lo_B
                #pragma unroll
                for (int g = 0; g < 2; ++g)
                    LDSM4(bx[g], sb + OFF_BL + swz((uint32_t)(wn + g * 16) + lrow, cseg));
                #pragma unroll
                for (int smi = 0; smi < 4; ++smi)
                    #pragma unroll
                    for (int sn = 0; sn < 4; ++sn) {
                        const int g = sn >> 1, s = sn & 1;
                        MMA16816(acc[smi][sn], ah[smi], bx[g][s], bx[g][s + 2]);
                    }
            }
        }
    }

    // --- epilogue
    #pragma unroll
    for (int smi = 0; smi < 4; ++smi) {
        const int gm0 = m0 + wm + smi * 16 + (lane >> 2);
        #pragma unroll
        for (int hr = 0; hr < 2; ++hr) {
            const int gm = gm0 + hr * 8;
            #pragma unroll
            for (int sn = 0; sn < 4; ++sn) {
                const int gn = n0 + wn + sn * 8 + 2 * (lane & 3);
                float v0 = acc[smi][sn][hr * 2 + 0];
                float v1 = acc[smi][sn][hr * 2 + 1];
                if (MODE == 0) {
                    v0 += bias[gn]; v1 += bias[gn + 1];
                    __half h0, h1, l0, l1;
                    split1(v0, h0, l0); split1(v1, h1, l1);
                    const size_t off = (size_t)bz * sOutB + (size_t)gm * 1024 + gn;
                    *reinterpret_cast<__half2*>(outHi + off) = __halves2half2(h0, h1);
                    *reinterpret_cast<__half2*>(outLo + off) = __halves2half2(l0, l1);
                } else if (MODE == 1) {
                    const size_t moff = (size_t)bz * sMask + (size_t)gm * 1024 + gn;
                    const float2 mk = *reinterpret_cast<const float2*>(&mask[moff]);
                    v0 += mk.x; v1 += mk.y;
                    const size_t off = (size_t)bz * sOutF + (size_t)gm * 1024 + gn;
                    float2 o; o.x = v0; o.y = v1;
                    *reinterpret_cast<float2*>(&outF[off]) = o;
                } else {
                    const size_t off = (size_t)bz * sOutF + (size_t)gm * 1024 + gn;
                    float2 o; o.x = v0; o.y = v1;
                    *reinterpret_cast<float2*>(&outF[off]) = o;
                }
            }
        }
    }
}

// ---------------------------------------------------------------------------
// fp32 -> fp16 hi/lo split (elementwise)
// ---------------------------------------------------------------------------
__global__ __launch_bounds__(256) void split_plain(
    const float* __restrict__ x, __half* __restrict__ hi,
    __half* __restrict__ lo, size_t n)
{
    const size_t i = ((size_t)blockIdx.x * 256 + threadIdx.x) * 4;
    if (i >= n) return;
    const float4 v = *reinterpret_cast<const float4*>(&x[i]);
    __half h0, h1, h2, h3, l0, l1, l2, l3;
    split1(v.x, h0, l0); split1(v.y, h1, l1);
    split1(v.z, h2, l2); split1(v.w, h3, l3);
    __half2 hv[2] = { __halves2half2(h0, h1), __halves2half2(h2, h3) };
    __half2 lv[2] = { __halves2half2(l0, l1), __halves2half2(l2, l3) };
    *reinterpret_cast<uint2*>(hi + i) = *reinterpret_cast<uint2*>(hv);
    *reinterpret_cast<uint2*>(lo + i) = *reinterpret_cast<uint2*>(lv);
}

// ---------------------------------------------------------------------------
// H: split to hi/lo AND transposed hi ([B][D2][LH])
// ---------------------------------------------------------------------------
__global__ __launch_bounds__(256) void split_h(
    const float* __restrict__ H,
    __half* __restrict__ Hhi, __half* __restrict__ Hlo,
    __half* __restrict__ Thi)
{
    __shared__ float tile[32][33];
    const int b = blockIdx.z;
    const int t0 = blockIdx.y * 32;   // LH dim
    const int e0 = blockIdx.x * 32;   // D2 dim
    const int tx = threadIdx.x & 31, ty = threadIdx.x >> 5;
    const size_t base = (size_t)b * PB;

    #pragma unroll
    for (int i = 0; i < 4; ++i) {
        const int r = ty + i * 8;
        const float v = H[base + (size_t)(t0 + r) * 1024 + e0 + tx];
        tile[r][tx] = v;
        __half h, l; split1(v, h, l);
        const size_t off = base + (size_t)(t0 + r) * 1024 + e0 + tx;
        Hhi[off] = h; Hlo[off] = l;
    }
    __syncthreads();
    #pragma unroll
    for (int i = 0; i < 4; ++i) {
        const int r = ty + i * 8;
        const float v = tile[tx][r];
        const size_t off = base + (size_t)(e0 + r) * 1024 + t0 + tx;
        Thi[off] = __float2half_rn(v);
    }
}

// ---------------------------------------------------------------------------
// Row softmax (len 1024) fp32 in, fp16 hi out (lo no longer needed)
// ---------------------------------------------------------------------------
__global__ __launch_bounds__(256) void softmax_h(
    const float* __restrict__ sc,
    __half* __restrict__ phi)
{
    __shared__ float red[8];
    const size_t row = blockIdx.x;
    const float* p = sc + row * 1024;
    const int tid = threadIdx.x, lane = tid & 31, wid = tid >> 5;

    float v[4];
    float mx = -INFINITY;
    #pragma unroll
    for (int i = 0; i < 4; i++) { v[i] = p[tid + i * 256]; mx = fmaxf(mx, v[i]); }
    #pragma unroll
    for (int off = 16; off > 0; off >>= 1)
        mx = fmaxf(mx, __shfl_xor_sync(0xffffffffu, mx, off));
    if (lane == 0) red[wid] = mx;
    __syncthreads();
    {
        float m = red[lane & 7];
        #pragma unroll
        for (int off = 4; off > 0; off >>= 1)
            m = fmaxf(m, __shfl_xor_sync(0xffffffffu, m, off));
        mx = m;
    }
    float s = 0.0f;
    #pragma unroll
    for (int i = 0; i < 4; i++) { v[i] = expf(v[i] - mx); s += v[i]; }
    #pragma unroll
    for (int off = 16; off > 0; off >>= 1)
        s += __shfl_xor_sync(0xffffffffu, s, off);
    __syncthreads();
    if (lane == 0) red[wid] = s;
    __syncthreads();
    {
        float t = red[lane & 7];
        #pragma unroll
        for (int off = 4; off > 0; off >>= 1)
            t += __shfl_xor_sync(0xffffffffu, t, off);
        s = t;
    }
    const float inv = 1.0f / s;
    #pragma unroll
    for (int i = 0; i < 4; i++)
        phi[row * 1024 + tid + i * 256] = __float2half_rn(v[i] * inv);
}

// ---------------------------------------------------------------------------
// Launch
// ---------------------------------------------------------------------------
extern "C" void kernel_launch(void* const* d_in, const int* in_sizes, int n_in,
                              void* d_out, int out_size)
{
    const float* S    = (const float*)d_in[0];
    const float* H    = (const float*)d_in[1];
    const float* mask = (const float*)d_in[2];
    const float* Ww   = (const float*)d_in[3];
    const float* Wb   = (const float*)d_in[4];
    float* out = (float*)d_out;

    __half *Shi, *Slo, *Whi, *Wlo, *Hhi, *Hlo, *Thi;
    __half *SPhi, *SPlo, *Phi;
    float* score;
    cudaGetSymbolAddress((void**)&Shi, g_Shi);   cudaGetSymbolAddress((void**)&Slo, g_Slo);
    cudaGetSymbolAddress((void**)&Whi, g_Whi);   cudaGetSymbolAddress((void**)&Wlo, g_Wlo);
    cudaGetSymbolAddress((void**)&Hhi, g_Hhi);   cudaGetSymbolAddress((void**)&Hlo, g_Hlo);
    cudaGetSymbolAddress((void**)&Thi, g_Thi);
    cudaGetSymbolAddress((void**)&SPhi, g_SPhi); cudaGetSymbolAddress((void**)&SPlo, g_SPlo);
    cudaGetSymbolAddress((void**)&Phi, g_Phi);
    cudaGetSymbolAddress((void**)&score, g_score);

    cudaFuncSetAttribute(gemm3x<0>, cudaFuncAttributeMaxDynamicSharedMemorySize, SMEM_BYTES);
    cudaFuncSetAttribute(gemm3x<1>, cudaFuncAttributeMaxDynamicSharedMemorySize, SMEM_BYTES);
    cudaFuncSetAttribute(gemm3x<2>, cudaFuncAttributeMaxDynamicSharedMemorySize, SMEM_BYTES);

    // splits
    split_plain<<<(unsigned)(ELEMS / 1024), 256>>>(S, Shi, Slo, ELEMS);
    split_plain<<<1024, 256>>>(Ww, Whi, Wlo, (size_t)1024 * 1024);
    split_h<<<dim3(32, 32, Bn), 256>>>(H, Hhi, Hlo, Thi);

    dim3 grid(8, 8, Bn);
    // 1) S_ = S @ W^T + b  (3-pass; W shared across batch: sB = 0)
    gemm3x<0><<<grid, 256, SMEM_BYTES>>>(Shi, Slo, Whi, Wlo, PB, 0,
                                         Wb, nullptr, 0, nullptr, 0, SPhi, SPlo, PB);
    // 2) score = S_ @ H^T + mask  (3-pass)
    gemm3x<1><<<grid, 256, SMEM_BYTES>>>(SPhi, SPlo, Hhi, Hlo, PB, PB,
                                         nullptr, mask, PB, score, PB, nullptr, nullptr, 0);
    // 3) softmax -> fp16 (hi only)
    softmax_h<<<Bn * 1024, 256>>>(score, Phi);
    // 4) out = P @ H  (1-pass: P_hi * H_hi; B = H^T hi)
    gemm3x<2><<<grid, 256, SMEM_BYTES>>>(Phi, nullptr, Thi, nullptr, PB, PB,
                                         nullptr, nullptr, 0, out, PB, nullptr, nullptr, 0);
}

// round 14
// speedup vs baseline: 1.2715x; 1.0123x over previous
#include <cuda_runtime.h>
#include <cuda_fp16.h>
#include <math.h>
#include <stdint.h>

// Problem constants
#define Bn    16
#define KDIM  1024
#define PB    ((size_t)1024 * 1024)

// GEMM tiling: CTA tile 128(M) x 64(N), warp tile 32x32, K chunks of 32 halves
#define BK      32
#define NCHUNK  (KDIM / BK)   // 32
#define ATILE_B 8192          // 128 rows x 64B
#define BTILE_B 4096          // 64 rows x 64B
#define OFF_AH  0
#define OFF_AL  (ATILE_B)
#define OFF_BH  (2 * ATILE_B)
#define OFF_BL  (2 * ATILE_B + BTILE_B)
#define STG_B   (2 * ATILE_B + 2 * BTILE_B)   // 24 KB / stage
#define NSTG    3
#define SMEM_BYTES (NSTG * STG_B)             // 72 KB  -> 3 CTAs/SM

// ---------------------------------------------------------------------------
// Device scratch
// ---------------------------------------------------------------------------
#define ELEMS ((size_t)Bn * 1024 * 1024)
__device__ __half g_Shi[ELEMS], g_Slo[ELEMS];
__device__ __half g_Whi[1024 * 1024], g_Wlo[1024 * 1024];
__device__ __half g_Hhi[ELEMS], g_Hlo[ELEMS];
__device__ __half g_Thi[ELEMS];                   // H transposed (hi only)
__device__ __half g_SPhi[ELEMS], g_SPlo[ELEMS];   // GEMM1 out
__device__ __half g_Phi[ELEMS];                   // softmax out (hi only)
__device__ float  g_score[ELEMS];

// ---------------------------------------------------------------------------
// Helpers
// ---------------------------------------------------------------------------
__device__ __forceinline__ uint32_t smem_u32(const void* p) {
    return (uint32_t)__cvta_generic_to_shared(p);
}
__device__ __forceinline__ void cp16(uint32_t dst, const void* src) {
    asm volatile("cp.async.cg.shared.global [%0], [%1], 16;\n"
                 :: "r"(dst), "l"(src) : "memory");
}
#define CP_COMMIT() asm volatile("cp.async.commit_group;\n" ::: "memory")
#define CP_WAIT(n)  asm volatile("cp.async.wait_group %0;\n" :: "n"(n) : "memory")

// Swizzled byte offset within a (rows x 32-half) tile (rows of 64B packed).
__device__ __forceinline__ uint32_t swz(uint32_t r, uint32_t c) {
    return (r >> 1) * 128u + (((((r & 1u) << 2) | (c ^ ((r >> 1) & 3u)))) << 4);
}

#define LDSM4(r, a)                                                            \
    asm volatile("ldmatrix.sync.aligned.m8n8.x4.shared.b16 {%0,%1,%2,%3}, [%4];" \
        : "=r"((r)[0]), "=r"((r)[1]), "=r"((r)[2]), "=r"((r)[3]) : "r"(a))

#define MMA16816(c, a, b0v, b1v)                                               \
    asm volatile("mma.sync.aligned.m16n8k16.row.col.f32.f16.f16.f32 "          \
        "{%0,%1,%2,%3}, {%4,%5,%6,%7}, {%8,%9}, {%0,%1,%2,%3};"                \
        : "+f"((c)[0]), "+f"((c)[1]), "+f"((c)[2]), "+f"((c)[3])               \
        : "r"((a)[0]), "r"((a)[1]), "r"((a)[2]), "r"((a)[3]),                  \
          "r"(b0v), "r"(b1v))

__device__ __forceinline__ void split1(float x, __half& h, __half& l) {
    h = __float2half_rn(x);
    l = __float2half_rn(x - __half2float(h));
}

// ---------------------------------------------------------------------------
// HMMA NT GEMM (C[m][n] = sum_k A[m][k]*B[n][k]), fp16 hi/lo split, f32 acc.
// CTA 128x64, warp 32x32, 3-stage cp.async pipeline, 3 CTAs/SM (reg-capped).
// MODE 0: 3-pass (hh + al*bh + ah*bl), +bias[n], write __half hi/lo.
// MODE 1: 3-pass, +mask, write fp32.
// MODE 2: 1-pass (hh only), write fp32. Alo/Blo unused.
// ---------------------------------------------------------------------------
template <int MODE>
__global__ __launch_bounds__(256, 3) void gemm3x(
    const __half* __restrict__ Ahi, const __half* __restrict__ Alo,
    const __half* __restrict__ Bhi, const __half* __restrict__ Blo,
    size_t sA, size_t sB,
    const float* __restrict__ bias,
    const float* __restrict__ mask, size_t sMask,
    float* __restrict__ outF, size_t sOutF,
    __half* __restrict__ outHi, __half* __restrict__ outLo, size_t sOutB)
{
    constexpr bool ONE_PASS = (MODE == 2);
    extern __shared__ __half sm[];

    const int tid  = threadIdx.x;
    const int lane = tid & 31;
    const int wid  = tid >> 5;
    const int m0 = blockIdx.y * 128, n0 = blockIdx.x * 64, bz = blockIdx.z;

    Ahi += (size_t)bz * sA;
    Bhi += (size_t)bz * sB;
    if (!ONE_PASS) { Alo += (size_t)bz * sA; Blo += (size_t)bz * sB; }

    const uint32_t sbase = smem_u32(sm);

    // --- gmem->smem loader mapping
    // A: 128 rows, thread -> (row = tid>>1, segs c0, c0+1)
    const int lrA = tid >> 1;
    const int c0  = (tid & 1) * 2;
    const uint32_t swA0 = swz((uint32_t)lrA, (uint32_t)c0);
    const uint32_t swA1 = swz((uint32_t)lrA, (uint32_t)c0 + 1);
    // B: 64 rows, thread -> (row = tid>>2, seg = tid&3)
    const int lrB = tid >> 2;
    const int sgB = tid & 3;
    const uint32_t swB0 = swz((uint32_t)lrB, (uint32_t)sgB);

    auto load_stage = [&](int c) {
        const uint32_t sb = sbase + (uint32_t)(c % NSTG) * STG_B;
        const size_t kofA = (size_t)c * BK + (size_t)c0 * 8;
        const __half* pah = Ahi + (size_t)(m0 + lrA) * KDIM + kofA;
        cp16(sb + OFF_AH + swA0, pah);
        cp16(sb + OFF_AH + swA1, pah + 8);
        const size_t kofB = (size_t)c * BK + (size_t)sgB * 8;
        cp16(sb + OFF_BH + swB0, Bhi + (size_t)(n0 + lrB) * KDIM + kofB);
        if (!ONE_PASS) {
            const __half* pal = Alo + (size_t)(m0 + lrA) * KDIM + kofA;
            cp16(sb + OFF_AL + swA0, pal);
            cp16(sb + OFF_AL + swA1, pal + 8);
            cp16(sb + OFF_BL + swB0, Blo + (size_t)(n0 + lrB) * KDIM + kofB);
        }
    };

    // --- per-warp compute mapping: warp tile 32(M) x 32(N)
    const int wm = (wid & 3) * 32;           // 4 M-groups over 128
    const int wn = (wid >> 2) * 32;          // 2 N-groups over 64
    const uint32_t lrow = (uint32_t)(lane & 15);
    const uint32_t chi  = (uint32_t)(lane >> 4);

    float acc[2][4][4];
    #pragma unroll
    for (int i = 0; i < 2; i++)
        #pragma unroll
        for (int j = 0; j < 4; j++)
            #pragma unroll
            for (int r = 0; r < 4; r++) acc[i][j][r] = 0.0f;

    // Prologue: stages 0, 1
    load_stage(0); CP_COMMIT();
    load_stage(1); CP_COMMIT();

    for (int c = 0; c < NCHUNK; ++c) {
        if (c == NCHUNK - 1) { CP_WAIT(0); } else { CP_WAIT(1); }
        __syncthreads();  // stage c visible; retires compute(c-1)
        if (c + 2 < NCHUNK) {
            load_stage(c + 2);
            CP_COMMIT();
        }

        const uint32_t sb = sbase + (uint32_t)(c % NSTG) * STG_B;
        #pragma unroll
        for (int ks = 0; ks < 2; ++ks) {
            const uint32_t cseg = (uint32_t)ks * 2 + chi;
            uint32_t ah[2][4], ax[2][4], bh[2][4], bx[2][4];

            // --- pass 1: hi * hi
            #pragma unroll
            for (int smi = 0; smi < 2; ++smi)
                LDSM4(ah[smi], sb + OFF_AH + swz((uint32_t)(wm + smi * 16) + lrow, cseg));
            #pragma unroll
            for (int g = 0; g < 2; ++g)
                LDSM4(bh[g], sb + OFF_BH + swz((uint32_t)(wn + g * 16) + lrow, cseg));
            #pragma unroll
            for (int smi = 0; smi < 2; ++smi)
                #pragma unroll
                for (int sn = 0; sn < 4; ++sn) {
                    const int g = sn >> 1, s = sn & 1;
                    MMA16816(acc[smi][sn], ah[smi], bh[g][s], bh[g][s + 2]);
                }

            if (!ONE_PASS) {
                // --- pass 2: lo_A * hi_B
                #pragma unroll
                for (int smi = 0; smi < 2; ++smi)
                    LDSM4(ax[smi], sb + OFF_AL + swz((uint32_t)(wm + smi * 16) + lrow, cseg));
                #pragma unroll
                for (int smi = 0; smi < 2; ++smi)
                    #pragma unroll
                    for (int sn = 0; sn < 4; ++sn) {
                        const int g = sn >> 1, s = sn & 1;
                        MMA16816(acc[smi][sn], ax[smi], bh[g][s], bh[g][s + 2]);
                    }

                // --- pass 3: hi_A * lo_B
                #pragma unroll
                for (int g = 0; g < 2; ++g)
                    LDSM4(bx[g], sb + OFF_BL + swz((uint32_t)(wn + g * 16) + lrow, cseg));
                #pragma unroll
                for (int smi = 0; smi < 2; ++smi)
                    #pragma unroll
                    for (int sn = 0; sn < 4; ++sn) {
                        const int g = sn >> 1, s = sn & 1;
                        MMA16816(acc[smi][sn], ah[smi], bx[g][s], bx[g][s + 2]);
                    }
            }
        }
    }

    // --- epilogue
    #pragma unroll
    for (int smi = 0; smi < 2; ++smi) {
        const int gm0 = m0 + wm + smi * 16 + (lane >> 2);
        #pragma unroll
        for (int hr = 0; hr < 2; ++hr) {
            const int gm = gm0 + hr * 8;
            #pragma unroll
            for (int sn = 0; sn < 4; ++sn) {
                const int gn = n0 + wn + sn * 8 + 2 * (lane & 3);
                float v0 = acc[smi][sn][hr * 2 + 0];
                float v1 = acc[smi][sn][hr * 2 + 1];
                if (MODE == 0) {
                    v0 += bias[gn]; v1 += bias[gn + 1];
                    __half h0, h1, l0, l1;
                    split1(v0, h0, l0); split1(v1, h1, l1);
                    const size_t off = (size_t)bz * sOutB + (size_t)gm * 1024 + gn;
                    *reinterpret_cast<__half2*>(outHi + off) = __halves2half2(h0, h1);
                    *reinterpret_cast<__half2*>(outLo + off) = __halves2half2(l0, l1);
                } else if (MODE == 1) {
                    const size_t moff = (size_t)bz * sMask + (size_t)gm * 1024 + gn;
                    const float2 mk = *reinterpret_cast<const float2*>(&mask[moff]);
                    v0 += mk.x; v1 += mk.y;
                    const size_t off = (size_t)bz * sOutF + (size_t)gm * 1024 + gn;
                    float2 o; o.x = v0; o.y = v1;
                    *reinterpret_cast<float2*>(&outF[off]) = o;
                } else {
                    const size_t off = (size_t)bz * sOutF + (size_t)gm * 1024 + gn;
                    float2 o; o.x = v0; o.y = v1;
                    *reinterpret_cast<float2*>(&outF[off]) = o;
                }
            }
        }
    }
}

// ---------------------------------------------------------------------------
// fp32 -> fp16 hi/lo split (elementwise)
// ---------------------------------------------------------------------------
__global__ __launch_bounds__(256) void split_plain(
    const float* __restrict__ x, __half* __restrict__ hi,
    __half* __restrict__ lo, size_t n)
{
    const size_t i = ((size_t)blockIdx.x * 256 + threadIdx.x) * 4;
    if (i >= n) return;
    const float4 v = *reinterpret_cast<const float4*>(&x[i]);
    __half h0, h1, h2, h3, l0, l1, l2, l3;
    split1(v.x, h0, l0); split1(v.y, h1, l1);
    split1(v.z, h2, l2); split1(v.w, h3, l3);
    __half2 hv[2] = { __halves2half2(h0, h1), __halves2half2(h2, h3) };
    __half2 lv[2] = { __halves2half2(l0, l1), __halves2half2(l2, l3) };
    *reinterpret_cast<uint2*>(hi + i) = *reinterpret_cast<uint2*>(hv);
    *reinterpret_cast<uint2*>(lo + i) = *reinterpret_cast<uint2*>(lv);
}

// ---------------------------------------------------------------------------
// H: split to hi/lo AND transposed hi ([B][D2][LH])
// ---------------------------------------------------------------------------
__global__ __launch_bounds__(256) void split_h(
    const float* __restrict__ H,
    __half* __restrict__ Hhi, __half* __restrict__ Hlo,
    __half* __restrict__ Thi)
{
    __shared__ float tile[32][33];
    const int b = blockIdx.z;
    const int t0 = blockIdx.y * 32;
    const int e0 = blockIdx.x * 32;
    const int tx = threadIdx.x & 31, ty = threadIdx.x >> 5;
    const size_t base = (size_t)b * PB;

    #pragma unroll
    for (int i = 0; i < 4; ++i) {
        const int r = ty + i * 8;
        const float v = H[base + (size_t)(t0 + r) * 1024 + e0 + tx];
        tile[r][tx] = v;
        __half h, l; split1(v, h, l);
        const size_t off = base + (size_t)(t0 + r) * 1024 + e0 + tx;
        Hhi[off] = h; Hlo[off] = l;
    }
    __syncthreads();
    #pragma unroll
    for (int i = 0; i < 4; ++i) {
        const int r = ty + i * 8;
        const float v = tile[tx][r];
        const size_t off = base + (size_t)(e0 + r) * 1024 + t0 + tx;
        Thi[off] = __float2half_rn(v);
    }
}

// ---------------------------------------------------------------------------
// Row softmax (len 1024) fp32 in, fp16 hi out
// ---------------------------------------------------------------------------
__global__ __launch_bounds__(256) void softmax_h(
    const float* __restrict__ sc,
    __half* __restrict__ phi)
{
    __shared__ float red[8];
    const size_t row = blockIdx.x;
    const float* p = sc + row * 1024;
    const int tid = threadIdx.x, lane = tid & 31, wid = tid >> 5;

    float v[4];
    float mx = -INFINITY;
    #pragma unroll
    for (int i = 0; i < 4; i++) { v[i] = p[tid + i * 256]; mx = fmaxf(mx, v[i]); }
    #pragma unroll
    for (int off = 16; off > 0; off >>= 1)
        mx = fmaxf(mx, __shfl_xor_sync(0xffffffffu, mx, off));
    if (lane == 0) red[wid] = mx;
    __syncthreads();
    {
        float m = red[lane & 7];
        #pragma unroll
        for (int off = 4; off > 0; off >>= 1)
            m = fmaxf(m, __shfl_xor_sync(0xffffffffu, m, off));
        mx = m;
    }
    float s = 0.0f;
    #pragma unroll
    for (int i = 0; i < 4; i++) { v[i] = expf(v[i] - mx); s += v[i]; }
    #pragma unroll
    for (int off = 16; off > 0; off >>= 1)
        s += __shfl_xor_sync(0xffffffffu, s, off);
    __syncthreads();
    if (lane == 0) red[wid] = s;
    __syncthreads();
    {
        float t = red[lane & 7];
        #pragma unroll
        for (int off = 4; off > 0; off >>= 1)
            t += __shfl_xor_sync(0xffffffffu, t, off);
        s = t;
    }
    const float inv = 1.0f / s;
    #pragma unroll
    for (int i = 0; i < 4; i++)
        phi[row * 1024 + tid + i * 256] = __float2half_rn(v[i] * inv);
}

// ---------------------------------------------------------------------------
// Launch
// ---------------------------------------------------------------------------
extern "C" void kernel_launch(void* const* d_in, const int* in_sizes, int n_in,
                              void* d_out, int out_size)
{
    const float* S    = (const float*)d_in[0];
    const float* H    = (const float*)d_in[1];
    const float* mask = (const float*)d_in[2];
    const float* Ww   = (const float*)d_in[3];
    const float* Wb   = (const float*)d_in[4];
    float* out = (float*)d_out;

    __half *Shi, *Slo, *Whi, *Wlo, *Hhi, *Hlo, *Thi;
    __half *SPhi, *SPlo, *Phi;
    float* score;
    cudaGetSymbolAddress((void**)&Shi, g_Shi);   cudaGetSymbolAddress((void**)&Slo, g_Slo);
    cudaGetSymbolAddress((void**)&Whi, g_Whi);   cudaGetSymbolAddress((void**)&Wlo, g_Wlo);
    cudaGetSymbolAddress((void**)&Hhi, g_Hhi);   cudaGetSymbolAddress((void**)&Hlo, g_Hlo);
    cudaGetSymbolAddress((void**)&Thi, g_Thi);
    cudaGetSymbolAddress((void**)&SPhi, g_SPhi); cudaGetSymbolAddress((void**)&SPlo, g_SPlo);
    cudaGetSymbolAddress((void**)&Phi, g_Phi);
    cudaGetSymbolAddress((void**)&score, g_score);

    cudaFuncSetAttribute(gemm3x<0>, cudaFuncAttributeMaxDynamicSharedMemorySize, SMEM_BYTES);
    cudaFuncSetAttribute(gemm3x<1>, cudaFuncAttributeMaxDynamicSharedMemorySize, SMEM_BYTES);
    cudaFuncSetAttribute(gemm3x<2>, cudaFuncAttributeMaxDynamicSharedMemorySize, SMEM_BYTES);

    // splits
    split_plain<<<(unsigned)(ELEMS / 1024), 256>>>(S, Shi, Slo, ELEMS);
    split_plain<<<1024, 256>>>(Ww, Whi, Wlo, (size_t)1024 * 1024);
    split_h<<<dim3(32, 32, Bn), 256>>>(H, Hhi, Hlo, Thi);

    dim3 grid(16, 8, Bn);   // 128x64 CTA tiles -> 2048 CTAs/GEMM
    // 1) S_ = S @ W^T + b  (3-pass; W shared across batch: sB = 0)
    gemm3x<0><<<grid, 256, SMEM_BYTES>>>(Shi, Slo, Whi, Wlo, PB, 0,
                                         Wb, nullptr, 0, nullptr, 0, SPhi, SPlo, PB);
    // 2) score = S_ @ H^T + mask  (3-pass)
    gemm3x<1><<<grid, 256, SMEM_BYTES>>>(SPhi, SPlo, Hhi, Hlo, PB, PB,
                                         nullptr, mask, PB, score, PB, nullptr, nullptr, 0);
    // 3) softmax -> fp16 (hi only)
    softmax_h<<<Bn * 1024, 256>>>(score, Phi);
    // 4) out = P @ H  (1-pass: P_hi * H_hi; B = H^T hi)
    gemm3x<2><<<grid, 256, SMEM_BYTES>>>(Phi, nullptr, Thi, nullptr, PB, PB,
                                         nullptr, nullptr, 0, out, PB, nullptr, nullptr, 0);
}